// round 2
// baseline (speedup 1.0000x reference)
#include <cuda_runtime.h>
#include <cuda_bf16.h>
#include <math.h>

// Problem constants
#define BB 2
#define TT 2048
#define CC 2048
#define HH 16
#define DKK 128
#define DVV 128
#define KEY_DIM 2048
#define VALUE_DIM 2048
#define CONV_DIM 6144
#define QKVZ_N 8192
#define BT 4096   // B*T

// ---------------- scratch (static device globals; no allocation) -------------
__device__ float g_qkvz[(size_t)BT * QKVZ_N];   // 128 MiB: x @ W_qkvz
__device__ float g_y[(size_t)BT * CONV_DIM];    // 96 MiB: conv+silu output, q/k l2-normalized
__device__ float g_beta[(size_t)BT * HH];
__device__ float g_alpha[(size_t)BT * HH];
__device__ float g_att[(size_t)BT * VALUE_DIM]; // 32 MiB recurrence output
__device__ float g_go[(size_t)BT * VALUE_DIM];  // 32 MiB gated/normed, input to W_out GEMM

// ---------------- SGEMM: C[M,N] = A[M,K] * B[K,N], all row-major -------------
// 128x128 block tile, BK=8, 256 threads, 8x8 microtile, software-pipelined
// global->smem (next tile's LDG issued before compute of current tile).
__global__ void __launch_bounds__(256, 2)
sgemm128(const float* __restrict__ A, const float* __restrict__ Bm,
         float* __restrict__ Cm, int M, int N, int Kd)
{
    __shared__ float As[8][128];
    __shared__ float Bs[8][128];

    const int tid = threadIdx.x;
    const int tx = tid & 15;       // 0..15 -> columns
    const int ty = tid >> 4;       // 0..15 -> rows
    const int bm = blockIdx.y * 128;
    const int bn = blockIdx.x * 128;

    // A tile loader: one float4 per thread: row am (0..127), k-offset ak (0 or 4)
    const int am = tid >> 1;
    const int ak = (tid & 1) * 4;
    // B tile loader: one float4 per thread: k-row bk (0..7), col bn4
    const int bk = tid >> 5;
    const int bn4 = (tid & 31) * 4;

    const float* Aptr = A + (size_t)(bm + am) * Kd + ak;
    const float* Bptr = Bm + (size_t)bk * N + bn + bn4;

    float c[8][8];
    #pragma unroll
    for (int i = 0; i < 8; i++)
        #pragma unroll
        for (int j = 0; j < 8; j++) c[i][j] = 0.f;

    float4 av = *(const float4*)Aptr;
    float4 bv = *(const float4*)Bptr;

    for (int k0 = 0; k0 < Kd; k0 += 8) {
        As[ak + 0][am] = av.x;
        As[ak + 1][am] = av.y;
        As[ak + 2][am] = av.z;
        As[ak + 3][am] = av.w;
        *(float4*)&Bs[bk][bn4] = bv;
        __syncthreads();

        // issue next tile's global loads before compute (latency hidden)
        Aptr += 8;
        Bptr += (size_t)8 * N;
        if (k0 + 8 < Kd) {
            av = *(const float4*)Aptr;
            bv = *(const float4*)Bptr;
        }

        #pragma unroll
        for (int kk = 0; kk < 8; kk++) {
            float a[8], b[8];
            *(float4*)&a[0] = *(const float4*)&As[kk][ty * 4];
            *(float4*)&a[4] = *(const float4*)&As[kk][64 + ty * 4];
            *(float4*)&b[0] = *(const float4*)&Bs[kk][tx * 4];
            *(float4*)&b[4] = *(const float4*)&Bs[kk][64 + tx * 4];
            #pragma unroll
            for (int i = 0; i < 8; i++)
                #pragma unroll
                for (int j = 0; j < 8; j++)
                    c[i][j] = fmaf(a[i], b[j], c[i][j]);
        }
        __syncthreads();
    }

    #pragma unroll
    for (int i = 0; i < 8; i++) {
        int row = bm + ((i < 4) ? (ty * 4 + i) : (64 + ty * 4 + (i - 4)));
        float* Crow = Cm + (size_t)row * N + bn;
        *(float4*)&Crow[tx * 4]      = make_float4(c[i][0], c[i][1], c[i][2], c[i][3]);
        *(float4*)&Crow[64 + tx * 4] = make_float4(c[i][4], c[i][5], c[i][6], c[i][7]);
    }
}

// ---------------- beta/alpha: sigmoid(x @ W_b), sigmoid(x @ W_a) -------------
// one block per row (bt), 128 threads = 32 groups of 4 lanes; groups 0..15 ->
// beta heads, 16..31 -> alpha heads.
__global__ void __launch_bounds__(128)
ba_kernel(const float* __restrict__ x, const float* __restrict__ Wb,
          const float* __restrict__ Wa, float* __restrict__ beta,
          float* __restrict__ alpha)
{
    __shared__ float xs[CC];
    const int row = blockIdx.x;
    const float* xr = x + (size_t)row * CC;
    for (int i = threadIdx.x; i < CC; i += 128) xs[i] = xr[i];
    __syncthreads();

    const int g = threadIdx.x >> 2;
    const int l = threadIdx.x & 3;
    const float* W = (g < 16) ? Wb : Wa;
    const int h = g & 15;
    float s = 0.f;
    for (int cidx = l; cidx < CC; cidx += 4)
        s = fmaf(xs[cidx], W[cidx * HH + h], s);
    s += __shfl_down_sync(0xffffffffu, s, 2);
    s += __shfl_down_sync(0xffffffffu, s, 1);
    if (l == 0) {
        float v = 1.f / (1.f + expf(-s));
        if (g < 16) beta[(size_t)row * HH + h] = v;
        else        alpha[(size_t)row * HH + h] = v;
    }
}

// ---------------- causal depthwise conv(K=4) + silu + l2norm of q,k ----------
// one block per (b,t); computes all 6144 channels, then normalizes the 16 q
// heads and 16 k heads, writes to g_y laid out [bt][6144].
__global__ void __launch_bounds__(256)
conv_kernel(const float* __restrict__ qkvz, const float* __restrict__ conv_w,
            const float* __restrict__ conv_state, const int* __restrict__ input_pos,
            float* __restrict__ y_out)
{
    __shared__ float ybuf[CONV_DIM];
    __shared__ float norms[32];

    const int bt = blockIdx.x;
    const int b = bt >> 11;       // /2048
    const int t = bt & 2047;
    const float keep = (input_pos[0] == 0) ? 0.f : 1.f;

    for (int c = threadIdx.x; c < CONV_DIM; c += 256) {
        float4 w = *(const float4*)&conv_w[c * 4];
        float in[4];
        #pragma unroll
        for (int j = 0; j < 4; j++) {
            int tau = t + j - 3;
            float v;
            if (tau >= 0) v = qkvz[((size_t)(b * TT + tau)) * QKVZ_N + c];
            else          v = keep * conv_state[((size_t)b * CONV_DIM + c) * 4 + (t + 1 + j)];
            in[j] = v;
        }
        float acc = in[0] * w.x + in[1] * w.y + in[2] * w.z + in[3] * w.w;
        float sig = 1.f / (1.f + expf(-acc));
        ybuf[c] = acc * sig;
    }
    __syncthreads();

    // 32 head-norms: heads 0..15 = q at [h*128], 16..31 = k at [2048+(h-16)*128]
    const int wid = threadIdx.x >> 5;
    const int lane = threadIdx.x & 31;
    for (int hh = wid; hh < 32; hh += 8) {
        int base = (hh < 16) ? hh * 128 : KEY_DIM + (hh - 16) * 128;
        float ss = 0.f;
        #pragma unroll
        for (int i = 0; i < 4; i++) {
            float v = ybuf[base + lane + i * 32];
            ss = fmaf(v, v, ss);
        }
        #pragma unroll
        for (int off = 16; off > 0; off >>= 1)
            ss += __shfl_xor_sync(0xffffffffu, ss, off);
        if (lane == 0) norms[hh] = fmaxf(sqrtf(ss), 1e-12f);
    }
    __syncthreads();

    float* yr = y_out + (size_t)bt * CONV_DIM;
    for (int c = threadIdx.x; c < CONV_DIM; c += 256) {
        float v = ybuf[c];
        if (c < 2 * KEY_DIM) v /= norms[c >> 7];
        yr[c] = v;
    }
}

// ---------------- gated linear-attention recurrence --------------------------
// grid (4, 32): blockIdx.y = b*16+h, blockIdx.x = dv block of 32.
// 256 threads: dvl = tid&31 (dv within block), dkg = tid>>5 (8 groups x 16 dk).
// Each thread holds 16 state values (dk range) for its dv column in registers.
__global__ void __launch_bounds__(256)
recur_kernel(const float* __restrict__ y, const float* __restrict__ beta,
             const float* __restrict__ alpha, const float* __restrict__ rstate,
             const int* __restrict__ input_pos, float* __restrict__ att)
{
    __shared__ float qs[128], ks[128], vs[32];
    __shared__ float red[8][33];

    const int bh = blockIdx.y;
    const int b = bh >> 4, h = bh & 15;
    const int dvb = blockIdx.x * 32;
    const int tid = threadIdx.x;
    const int dvl = tid & 31;
    const int dkg = tid >> 5;
    const int dv = dvb + dvl;
    const float keep = (input_pos[0] == 0) ? 0.f : 1.f;

    float s[16];
    #pragma unroll
    for (int i = 0; i < 16; i++)
        s[i] = keep * rstate[((size_t)bh * 128 + (dkg * 16 + i)) * 128 + dv];

    const float* ybase = y + (size_t)b * TT * CONV_DIM + h * 128;
    const float* arow = alpha + (size_t)b * TT * HH + h;
    const float* brow = beta  + (size_t)b * TT * HH + h;

    for (int t = 0; t < TT; t++) {
        const float* yr = ybase + (size_t)t * CONV_DIM;
        if (tid < 128) qs[tid] = yr[tid];
        else           ks[tid - 128] = yr[KEY_DIM + (tid - 128)];
        if (tid < 32)  vs[tid] = yr[2 * KEY_DIM + dvb + tid];
        __syncthreads();

        float a = arow[(size_t)t * HH];
        float bta = brow[(size_t)t * HH];
        float bv = bta * vs[dvl];
        float po = 0.f;
        #pragma unroll
        for (int i = 0; i < 16; i++) {
            int dk = dkg * 16 + i;
            s[i] = fmaf(a, s[i], bv * ks[dk]);
            po = fmaf(qs[dk], s[i], po);
        }
        red[dkg][dvl] = po;
        __syncthreads();
        if (dkg == 0) {
            float o = 0.f;
            #pragma unroll
            for (int g = 0; g < 8; g++) o += red[g][dvl];
            att[((size_t)(b * TT + t)) * VALUE_DIM + h * 128 + dv] = o;
        }
    }
}

// ---------------- rmsnorm * norm_w * sigmoid(z) ------------------------------
__global__ void __launch_bounds__(256)
gate_kernel(const float* __restrict__ att, const float* __restrict__ qkvz,
            const float* __restrict__ norm_w, float* __restrict__ go)
{
    const int bt = blockIdx.x;
    const int wid = threadIdx.x >> 5;
    const int lane = threadIdx.x & 31;

    #pragma unroll
    for (int k = 0; k < 2; k++) {
        const int hh = wid * 2 + k;
        const float* ar = att + (size_t)bt * VALUE_DIM + hh * 128;
        float v[4];
        float ss = 0.f;
        #pragma unroll
        for (int i = 0; i < 4; i++) {
            v[i] = ar[lane + i * 32];
            ss = fmaf(v[i], v[i], ss);
        }
        #pragma unroll
        for (int off = 16; off > 0; off >>= 1)
            ss += __shfl_xor_sync(0xffffffffu, ss, off);
        float scale = rsqrtf(ss * (1.f / 128.f) + 1e-6f);
        const float* zr = qkvz + (size_t)bt * QKVZ_N + CONV_DIM + hh * 128;
        float* gr = go + (size_t)bt * VALUE_DIM + hh * 128;
        #pragma unroll
        for (int i = 0; i < 4; i++) {
            int dvi = lane + i * 32;
            float z = zr[dvi];
            float sig = 1.f / (1.f + expf(-z));
            gr[dvi] = v[i] * scale * norm_w[dvi] * sig;
        }
    }
}

// ---------------- launch -----------------------------------------------------
extern "C" void kernel_launch(void* const* d_in, const int* in_sizes, int n_in,
                              void* d_out, int out_size)
{
    const float* x          = (const float*)d_in[0];
    const int*   input_pos  = (const int*)  d_in[1];
    const float* W_qkvz     = (const float*)d_in[2];
    const float* W_b        = (const float*)d_in[3];
    const float* W_a        = (const float*)d_in[4];
    const float* conv_w     = (const float*)d_in[5];
    const float* norm_w     = (const float*)d_in[6];
    const float* W_out      = (const float*)d_in[7];
    const float* conv_state = (const float*)d_in[8];
    const float* rec_state  = (const float*)d_in[9];
    float* out = (float*)d_out;

    float *qkvz, *y, *beta, *alpha, *attb, *gob;
    cudaGetSymbolAddress((void**)&qkvz, g_qkvz);
    cudaGetSymbolAddress((void**)&y,    g_y);
    cudaGetSymbolAddress((void**)&beta, g_beta);
    cudaGetSymbolAddress((void**)&alpha,g_alpha);
    cudaGetSymbolAddress((void**)&attb, g_att);
    cudaGetSymbolAddress((void**)&gob,  g_go);

    // 1) qkvz = x @ W_qkvz      (4096 x 8192 x 2048)
    sgemm128<<<dim3(QKVZ_N / 128, BT / 128), 256>>>(x, W_qkvz, qkvz, BT, QKVZ_N, CC);
    // 2) beta/alpha
    ba_kernel<<<BT, 128>>>(x, W_b, W_a, beta, alpha);
    // 3) conv + silu + l2norm
    conv_kernel<<<BT, 256>>>(qkvz, conv_w, conv_state, input_pos, y);
    // 4) recurrence
    recur_kernel<<<dim3(4, 32), 256>>>(y, beta, alpha, rec_state, input_pos, attb);
    // 5) rmsnorm + gate
    gate_kernel<<<BT, 256>>>(attb, qkvz, norm_w, gob);
    // 6) out = gated @ W_out    (4096 x 2048 x 2048)
    sgemm128<<<dim3(CC / 128, BT / 128), 256>>>(gob, W_out, out, BT, CC, CC);
}

// round 3
// speedup vs baseline: 1.2670x; 1.2670x over previous
#include <cuda_runtime.h>
#include <cuda_bf16.h>
#include <math.h>

// Problem constants
#define BB 2
#define TT 2048
#define CC 2048
#define HH 16
#define DKK 128
#define DVV 128
#define KEY_DIM 2048
#define VALUE_DIM 2048
#define CONV_DIM 6144
#define QKVZ_N 8192
#define BT 4096   // B*T

// ---------------- scratch (static device globals; no allocation) -------------
__device__ float g_qkvz[(size_t)BT * QKVZ_N];   // 128 MiB: x @ W_qkvz
__device__ float g_y[(size_t)BT * CONV_DIM];    // 96 MiB: conv+silu output, q/k l2-normalized
__device__ float g_beta[(size_t)BT * HH];
__device__ float g_alpha[(size_t)BT * HH];
__device__ float g_att[(size_t)BT * VALUE_DIM]; // 32 MiB recurrence output
__device__ float g_go[(size_t)BT * VALUE_DIM];  // 32 MiB gated/normed, input to W_out GEMM

// ---------------- tf32 tensor-core GEMM --------------------------------------
// C[M,N] = A[M,K] * B[K,N], row-major. 128x128 block tile, BK=16, 256 threads
// (8 warps as 2x4), warp tile 64x32, mma.sync.m16n8k8.tf32, fp32 accumulate.
__device__ __forceinline__ unsigned f2tf32(float x) {
    unsigned r;
    asm("cvt.rna.tf32.f32 %0, %1;" : "=r"(r) : "f"(x));
    return r;
}

__device__ __forceinline__ void mma_tf32(float* d, const unsigned* a,
                                         const unsigned* b) {
    asm volatile(
        "mma.sync.aligned.m16n8k8.row.col.f32.tf32.tf32.f32 "
        "{%0,%1,%2,%3}, {%4,%5,%6,%7}, {%8,%9}, {%0,%1,%2,%3};\n"
        : "+f"(d[0]), "+f"(d[1]), "+f"(d[2]), "+f"(d[3])
        : "r"(a[0]), "r"(a[1]), "r"(a[2]), "r"(a[3]),
          "r"(b[0]), "r"(b[1]));
}

__global__ void __launch_bounds__(256)
tf32gemm(const float* __restrict__ A, const float* __restrict__ Bm,
         float* __restrict__ Cm, int M, int N, int Kd)
{
    __shared__ unsigned As[16][132];   // [k][m], pad 4 to break conflicts
    __shared__ unsigned Bs[16][132];   // [k][n]

    const int tid  = threadIdx.x;
    const int bm   = blockIdx.y * 128;
    const int bn   = blockIdx.x * 128;
    const int lane = tid & 31;
    const int warp = tid >> 5;
    const int wm   = (warp >> 2) * 64;   // warp row offset (0 / 64)
    const int wn   = (warp & 3) * 32;    // warp col offset (0/32/64/96)
    const int tig  = lane & 3;           // thread-in-group
    const int gid  = lane >> 2;          // group id (0..7)

    // A loader: row am (0..127), k-chunks ac and ac+8 (float4 each)
    const int am = tid & 127;
    const int ac = (tid >> 7) * 4;
    // B loader: k rows bk and bk+8, 4 cols at bc
    const int bk = tid >> 5;
    const int bc = lane * 4;

    const float* Ap = A  + (size_t)(bm + am) * Kd + ac;
    const float* Bp = Bm + (size_t)bk * N + bn + bc;

    float acc[4][4][4];
    #pragma unroll
    for (int i = 0; i < 4; i++)
        #pragma unroll
        for (int j = 0; j < 4; j++)
            #pragma unroll
            for (int r = 0; r < 4; r++) acc[i][j][r] = 0.f;

    float4 av1 = *(const float4*)Ap;
    float4 av2 = *(const float4*)(Ap + 8);
    float4 bv1 = *(const float4*)Bp;
    float4 bv2 = *(const float4*)(Bp + (size_t)8 * N);

    for (int k0 = 0; k0 < Kd; k0 += 16) {
        As[ac + 0][am] = f2tf32(av1.x);
        As[ac + 1][am] = f2tf32(av1.y);
        As[ac + 2][am] = f2tf32(av1.z);
        As[ac + 3][am] = f2tf32(av1.w);
        As[ac + 8][am] = f2tf32(av2.x);
        As[ac + 9][am] = f2tf32(av2.y);
        As[ac + 10][am] = f2tf32(av2.z);
        As[ac + 11][am] = f2tf32(av2.w);
        {
            uint4 u1 = make_uint4(f2tf32(bv1.x), f2tf32(bv1.y), f2tf32(bv1.z), f2tf32(bv1.w));
            uint4 u2 = make_uint4(f2tf32(bv2.x), f2tf32(bv2.y), f2tf32(bv2.z), f2tf32(bv2.w));
            *(uint4*)&Bs[bk][bc]     = u1;
            *(uint4*)&Bs[bk + 8][bc] = u2;
        }
        __syncthreads();

        Ap += 16;
        Bp += (size_t)16 * N;
        if (k0 + 16 < Kd) {
            av1 = *(const float4*)Ap;
            av2 = *(const float4*)(Ap + 8);
            bv1 = *(const float4*)Bp;
            bv2 = *(const float4*)(Bp + (size_t)8 * N);
        }

        #pragma unroll
        for (int ks = 0; ks < 16; ks += 8) {
            unsigned af[4][4], bf[4][2];
            #pragma unroll
            for (int mt = 0; mt < 4; mt++) {
                const int mb = wm + mt * 16;
                af[mt][0] = As[ks + tig][mb + gid];
                af[mt][1] = As[ks + tig][mb + gid + 8];
                af[mt][2] = As[ks + tig + 4][mb + gid];
                af[mt][3] = As[ks + tig + 4][mb + gid + 8];
            }
            #pragma unroll
            for (int nt = 0; nt < 4; nt++) {
                const int nb = wn + nt * 8;
                bf[nt][0] = Bs[ks + tig][nb + gid];
                bf[nt][1] = Bs[ks + tig + 4][nb + gid];
            }
            #pragma unroll
            for (int mt = 0; mt < 4; mt++)
                #pragma unroll
                for (int nt = 0; nt < 4; nt++)
                    mma_tf32(acc[mt][nt], af[mt], bf[nt]);
        }
        __syncthreads();
    }

    // epilogue: c0/c1 at (row, 2*tig), c2/c3 at (row+8, 2*tig)
    #pragma unroll
    for (int mt = 0; mt < 4; mt++) {
        const int row = bm + wm + mt * 16 + gid;
        #pragma unroll
        for (int nt = 0; nt < 4; nt++) {
            const int col = bn + wn + nt * 8 + 2 * tig;
            *(float2*)&Cm[(size_t)row * N + col]       = make_float2(acc[mt][nt][0], acc[mt][nt][1]);
            *(float2*)&Cm[(size_t)(row + 8) * N + col] = make_float2(acc[mt][nt][2], acc[mt][nt][3]);
        }
    }
}

// ---------------- beta/alpha: sigmoid(x @ W_b), sigmoid(x @ W_a) -------------
__global__ void __launch_bounds__(128)
ba_kernel(const float* __restrict__ x, const float* __restrict__ Wb,
          const float* __restrict__ Wa, float* __restrict__ beta,
          float* __restrict__ alpha)
{
    __shared__ float xs[CC];
    const int row = blockIdx.x;
    const float* xr = x + (size_t)row * CC;
    for (int i = threadIdx.x; i < CC; i += 128) xs[i] = xr[i];
    __syncthreads();

    const int g = threadIdx.x >> 2;
    const int l = threadIdx.x & 3;
    const float* W = (g < 16) ? Wb : Wa;
    const int h = g & 15;
    float s = 0.f;
    for (int cidx = l; cidx < CC; cidx += 4)
        s = fmaf(xs[cidx], W[cidx * HH + h], s);
    s += __shfl_down_sync(0xffffffffu, s, 2);
    s += __shfl_down_sync(0xffffffffu, s, 1);
    if (l == 0) {
        float v = 1.f / (1.f + expf(-s));
        if (g < 16) beta[(size_t)row * HH + h] = v;
        else        alpha[(size_t)row * HH + h] = v;
    }
}

// ---------------- causal depthwise conv(K=4) + silu + l2norm of q,k ----------
__global__ void __launch_bounds__(256)
conv_kernel(const float* __restrict__ qkvz, const float* __restrict__ conv_w,
            const float* __restrict__ conv_state, const int* __restrict__ input_pos,
            float* __restrict__ y_out)
{
    __shared__ float ybuf[CONV_DIM];
    __shared__ float norms[32];

    const int bt = blockIdx.x;
    const int b = bt >> 11;
    const int t = bt & 2047;
    const float keep = (input_pos[0] == 0) ? 0.f : 1.f;

    for (int c = threadIdx.x; c < CONV_DIM; c += 256) {
        float4 w = *(const float4*)&conv_w[c * 4];
        float in[4];
        #pragma unroll
        for (int j = 0; j < 4; j++) {
            int tau = t + j - 3;
            float v;
            if (tau >= 0) v = qkvz[((size_t)(b * TT + tau)) * QKVZ_N + c];
            else          v = keep * conv_state[((size_t)b * CONV_DIM + c) * 4 + (t + 1 + j)];
            in[j] = v;
        }
        float acc = in[0] * w.x + in[1] * w.y + in[2] * w.z + in[3] * w.w;
        float sig = 1.f / (1.f + expf(-acc));
        ybuf[c] = acc * sig;
    }
    __syncthreads();

    const int wid = threadIdx.x >> 5;
    const int lane = threadIdx.x & 31;
    for (int hh = wid; hh < 32; hh += 8) {
        int base = (hh < 16) ? hh * 128 : KEY_DIM + (hh - 16) * 128;
        float ss = 0.f;
        #pragma unroll
        for (int i = 0; i < 4; i++) {
            float v = ybuf[base + lane + i * 32];
            ss = fmaf(v, v, ss);
        }
        #pragma unroll
        for (int off = 16; off > 0; off >>= 1)
            ss += __shfl_xor_sync(0xffffffffu, ss, off);
        if (lane == 0) norms[hh] = fmaxf(sqrtf(ss), 1e-12f);
    }
    __syncthreads();

    float* yr = y_out + (size_t)bt * CONV_DIM;
    for (int c = threadIdx.x; c < CONV_DIM; c += 256) {
        float v = ybuf[c];
        if (c < 2 * KEY_DIM) v /= norms[c >> 7];
        yr[c] = v;
    }
}

// ---------------- gated linear-attention recurrence --------------------------
__global__ void __launch_bounds__(256)
recur_kernel(const float* __restrict__ y, const float* __restrict__ beta,
             const float* __restrict__ alpha, const float* __restrict__ rstate,
             const int* __restrict__ input_pos, float* __restrict__ att)
{
    __shared__ float qs[128], ks[128], vs[32];
    __shared__ float red[8][33];

    const int bh = blockIdx.y;
    const int b = bh >> 4, h = bh & 15;
    const int dvb = blockIdx.x * 32;
    const int tid = threadIdx.x;
    const int dvl = tid & 31;
    const int dkg = tid >> 5;
    const int dv = dvb + dvl;
    const float keep = (input_pos[0] == 0) ? 0.f : 1.f;

    float s[16];
    #pragma unroll
    for (int i = 0; i < 16; i++)
        s[i] = keep * rstate[((size_t)bh * 128 + (dkg * 16 + i)) * 128 + dv];

    const float* ybase = y + (size_t)b * TT * CONV_DIM + h * 128;
    const float* arow = alpha + (size_t)b * TT * HH + h;
    const float* brow = beta  + (size_t)b * TT * HH + h;

    for (int t = 0; t < TT; t++) {
        const float* yr = ybase + (size_t)t * CONV_DIM;
        if (tid < 128) qs[tid] = yr[tid];
        else           ks[tid - 128] = yr[KEY_DIM + (tid - 128)];
        if (tid < 32)  vs[tid] = yr[2 * KEY_DIM + dvb + tid];
        __syncthreads();

        float a = arow[(size_t)t * HH];
        float bta = brow[(size_t)t * HH];
        float bv = bta * vs[dvl];
        float po = 0.f;
        #pragma unroll
        for (int i = 0; i < 16; i++) {
            int dk = dkg * 16 + i;
            s[i] = fmaf(a, s[i], bv * ks[dk]);
            po = fmaf(qs[dk], s[i], po);
        }
        red[dkg][dvl] = po;
        __syncthreads();
        if (dkg == 0) {
            float o = 0.f;
            #pragma unroll
            for (int g = 0; g < 8; g++) o += red[g][dvl];
            att[((size_t)(b * TT + t)) * VALUE_DIM + h * 128 + dv] = o;
        }
    }
}

// ---------------- rmsnorm * norm_w * sigmoid(z) ------------------------------
__global__ void __launch_bounds__(256)
gate_kernel(const float* __restrict__ att, const float* __restrict__ qkvz,
            const float* __restrict__ norm_w, float* __restrict__ go)
{
    const int bt = blockIdx.x;
    const int wid = threadIdx.x >> 5;
    const int lane = threadIdx.x & 31;

    #pragma unroll
    for (int k = 0; k < 2; k++) {
        const int hh = wid * 2 + k;
        const float* ar = att + (size_t)bt * VALUE_DIM + hh * 128;
        float v[4];
        float ss = 0.f;
        #pragma unroll
        for (int i = 0; i < 4; i++) {
            v[i] = ar[lane + i * 32];
            ss = fmaf(v[i], v[i], ss);
        }
        #pragma unroll
        for (int off = 16; off > 0; off >>= 1)
            ss += __shfl_xor_sync(0xffffffffu, ss, off);
        float scale = rsqrtf(ss * (1.f / 128.f) + 1e-6f);
        const float* zr = qkvz + (size_t)bt * QKVZ_N + CONV_DIM + hh * 128;
        float* gr = go + (size_t)bt * VALUE_DIM + hh * 128;
        #pragma unroll
        for (int i = 0; i < 4; i++) {
            int dvi = lane + i * 32;
            float z = zr[dvi];
            float sig = 1.f / (1.f + expf(-z));
            gr[dvi] = v[i] * scale * norm_w[dvi] * sig;
        }
    }
}

// ---------------- launch -----------------------------------------------------
extern "C" void kernel_launch(void* const* d_in, const int* in_sizes, int n_in,
                              void* d_out, int out_size)
{
    const float* x          = (const float*)d_in[0];
    const int*   input_pos  = (const int*)  d_in[1];
    const float* W_qkvz     = (const float*)d_in[2];
    const float* W_b        = (const float*)d_in[3];
    const float* W_a        = (const float*)d_in[4];
    const float* conv_w     = (const float*)d_in[5];
    const float* norm_w     = (const float*)d_in[6];
    const float* W_out      = (const float*)d_in[7];
    const float* conv_state = (const float*)d_in[8];
    const float* rec_state  = (const float*)d_in[9];
    float* out = (float*)d_out;

    float *qkvz, *y, *beta, *alpha, *attb, *gob;
    cudaGetSymbolAddress((void**)&qkvz, g_qkvz);
    cudaGetSymbolAddress((void**)&y,    g_y);
    cudaGetSymbolAddress((void**)&beta, g_beta);
    cudaGetSymbolAddress((void**)&alpha,g_alpha);
    cudaGetSymbolAddress((void**)&attb, g_att);
    cudaGetSymbolAddress((void**)&gob,  g_go);

    // 1) qkvz = x @ W_qkvz      (4096 x 8192 x 2048), tf32 tensor cores
    tf32gemm<<<dim3(QKVZ_N / 128, BT / 128), 256>>>(x, W_qkvz, qkvz, BT, QKVZ_N, CC);
    // 2) beta/alpha
    ba_kernel<<<BT, 128>>>(x, W_b, W_a, beta, alpha);
    // 3) conv + silu + l2norm
    conv_kernel<<<BT, 256>>>(qkvz, conv_w, conv_state, input_pos, y);
    // 4) recurrence
    recur_kernel<<<dim3(4, 32), 256>>>(y, beta, alpha, rec_state, input_pos, attb);
    // 5) rmsnorm + gate
    gate_kernel<<<BT, 256>>>(attb, qkvz, norm_w, gob);
    // 6) out = gated @ W_out    (4096 x 2048 x 2048), tf32 tensor cores
    tf32gemm<<<dim3(CC / 128, BT / 128), 256>>>(gob, W_out, out, BT, CC, CC);
}

// round 4
// speedup vs baseline: 1.5655x; 1.2355x over previous
#include <cuda_runtime.h>
#include <cuda_bf16.h>
#include <math.h>

// Problem constants
#define BB 2
#define TT 2048
#define CC 2048
#define HH 16
#define DKK 128
#define DVV 128
#define KEY_DIM 2048
#define VALUE_DIM 2048
#define CONV_DIM 6144
#define QKVZ_N 8192
#define BT 4096   // B*T

// ---------------- scratch (static device globals; no allocation) -------------
__device__ float g_qkvz[(size_t)BT * QKVZ_N];   // 128 MiB: x @ W_qkvz
__device__ float g_y[(size_t)BT * CONV_DIM];    // 96 MiB
__device__ float g_beta[(size_t)BT * HH];
__device__ float g_alpha[(size_t)BT * HH];
__device__ float g_att[(size_t)BT * VALUE_DIM]; // 32 MiB
__device__ float g_go[(size_t)BT * VALUE_DIM];  // 32 MiB

// ---------------- tf32 tensor-core GEMM --------------------------------------
// C[M,N] = A[M,K] * B[K,N], row-major. CTA tile 128x256, BK=16, 256 threads,
// 8 warps as 2x4, warp tile 64x64. Double-buffered smem, XOR bank swizzle
// (col ^ ((k&3)<<3)) => conflict-free fragment reads, 48KB smem exactly.
__device__ __forceinline__ unsigned f2tf32(float x) {
    unsigned r;
    asm("cvt.rna.tf32.f32 %0, %1;" : "=r"(r) : "f"(x));
    return r;
}

__device__ __forceinline__ void mma_tf32(float* d, const unsigned* a,
                                         const unsigned* b) {
    asm volatile(
        "mma.sync.aligned.m16n8k8.row.col.f32.tf32.tf32.f32 "
        "{%0,%1,%2,%3}, {%4,%5,%6,%7}, {%8,%9}, {%0,%1,%2,%3};\n"
        : "+f"(d[0]), "+f"(d[1]), "+f"(d[2]), "+f"(d[3])
        : "r"(a[0]), "r"(a[1]), "r"(a[2]), "r"(a[3]),
          "r"(b[0]), "r"(b[1]));
}

__global__ void __launch_bounds__(256)
tf32gemm(const float* __restrict__ A, const float* __restrict__ Bm,
         float* __restrict__ Cm, int M, int N, int Kd)
{
    __shared__ unsigned As[2][16][128];   // [buf][k][m^swz]  16 KB
    __shared__ unsigned Bs[2][16][256];   // [buf][k][n^swz]  32 KB

    const int tid  = threadIdx.x;
    const int bm   = blockIdx.y * 128;
    const int bn   = blockIdx.x * 256;
    const int lane = tid & 31;
    const int warp = tid >> 5;
    const int wm   = (warp >> 2) * 64;    // 0 / 64
    const int wn   = (warp & 3) * 64;     // 0 / 64 / 128 / 192
    const int tig  = lane & 3;
    const int gid  = lane >> 2;
    const int fsw  = tig << 3;            // fragment-read swizzle

    // A loader: row ar (0..127), k-base ka (0 or 8); lane pairs cover 64B rows
    const int ar = tid >> 1;
    const int ka = (tid & 1) * 8;
    // B loader: k-row br (0..15), col base bc, 4 float4 chunks 64 apart
    const int br = tid >> 4;
    const int bc = (tid & 15) * 4;
    const int bsw = (br & 3) << 3;

    const float* Ap = A  + (size_t)(bm + ar) * Kd + ka;
    const float* Bp = Bm + (size_t)br * N + bn + bc;

    float acc[4][8][4];
    #pragma unroll
    for (int i = 0; i < 4; i++)
        #pragma unroll
        for (int j = 0; j < 8; j++)
            #pragma unroll
            for (int r = 0; r < 4; r++) acc[i][j][r] = 0.f;

    float4 av0, av1, bv0, bv1, bv2, bv3;
    av0 = *(const float4*)Ap;
    av1 = *(const float4*)(Ap + 4);
    bv0 = *(const float4*)(Bp);
    bv1 = *(const float4*)(Bp + 64);
    bv2 = *(const float4*)(Bp + 128);
    bv3 = *(const float4*)(Bp + 192);

    // store tile into buffer 0
    {
        float a8[8] = {av0.x, av0.y, av0.z, av0.w, av1.x, av1.y, av1.z, av1.w};
        #pragma unroll
        for (int j = 0; j < 8; j++)
            As[0][ka + j][ar ^ (((ka + j) & 3) << 3)] = f2tf32(a8[j]);
        uint4 u;
        u = make_uint4(f2tf32(bv0.x), f2tf32(bv0.y), f2tf32(bv0.z), f2tf32(bv0.w));
        *(uint4*)&Bs[0][br][(bc +   0) ^ bsw] = u;
        u = make_uint4(f2tf32(bv1.x), f2tf32(bv1.y), f2tf32(bv1.z), f2tf32(bv1.w));
        *(uint4*)&Bs[0][br][(bc +  64) ^ bsw] = u;
        u = make_uint4(f2tf32(bv2.x), f2tf32(bv2.y), f2tf32(bv2.z), f2tf32(bv2.w));
        *(uint4*)&Bs[0][br][(bc + 128) ^ bsw] = u;
        u = make_uint4(f2tf32(bv3.x), f2tf32(bv3.y), f2tf32(bv3.z), f2tf32(bv3.w));
        *(uint4*)&Bs[0][br][(bc + 192) ^ bsw] = u;
    }
    __syncthreads();

    int buf = 0;
    for (int k0 = 0; k0 < Kd; k0 += 16) {
        const bool more = (k0 + 16) < Kd;
        if (more) {
            Ap += 16;
            Bp += (size_t)16 * N;
            av0 = *(const float4*)Ap;
            av1 = *(const float4*)(Ap + 4);
            bv0 = *(const float4*)(Bp);
            bv1 = *(const float4*)(Bp + 64);
            bv2 = *(const float4*)(Bp + 128);
            bv3 = *(const float4*)(Bp + 192);
        }

        #pragma unroll
        for (int ks = 0; ks < 16; ks += 8) {
            const int kr0 = ks + tig;
            const int kr1 = ks + tig + 4;
            unsigned af[4][4], bf[8][2];
            #pragma unroll
            for (int mt = 0; mt < 4; mt++) {
                const int mb = wm + mt * 16;
                af[mt][0] = As[buf][kr0][(mb + gid)     ^ fsw];
                af[mt][1] = As[buf][kr0][(mb + gid + 8) ^ fsw];
                af[mt][2] = As[buf][kr1][(mb + gid)     ^ fsw];
                af[mt][3] = As[buf][kr1][(mb + gid + 8) ^ fsw];
            }
            #pragma unroll
            for (int nt = 0; nt < 8; nt++) {
                const int nb = wn + nt * 8;
                bf[nt][0] = Bs[buf][kr0][(nb + gid) ^ fsw];
                bf[nt][1] = Bs[buf][kr1][(nb + gid) ^ fsw];
            }
            #pragma unroll
            for (int mt = 0; mt < 4; mt++)
                #pragma unroll
                for (int nt = 0; nt < 8; nt++)
                    mma_tf32(acc[mt][nt], af[mt], bf[nt]);
        }

        if (more) {
            const int nb2 = buf ^ 1;
            float a8[8] = {av0.x, av0.y, av0.z, av0.w, av1.x, av1.y, av1.z, av1.w};
            #pragma unroll
            for (int j = 0; j < 8; j++)
                As[nb2][ka + j][ar ^ (((ka + j) & 3) << 3)] = f2tf32(a8[j]);
            uint4 u;
            u = make_uint4(f2tf32(bv0.x), f2tf32(bv0.y), f2tf32(bv0.z), f2tf32(bv0.w));
            *(uint4*)&Bs[nb2][br][(bc +   0) ^ bsw] = u;
            u = make_uint4(f2tf32(bv1.x), f2tf32(bv1.y), f2tf32(bv1.z), f2tf32(bv1.w));
            *(uint4*)&Bs[nb2][br][(bc +  64) ^ bsw] = u;
            u = make_uint4(f2tf32(bv2.x), f2tf32(bv2.y), f2tf32(bv2.z), f2tf32(bv2.w));
            *(uint4*)&Bs[nb2][br][(bc + 128) ^ bsw] = u;
            u = make_uint4(f2tf32(bv3.x), f2tf32(bv3.y), f2tf32(bv3.z), f2tf32(bv3.w));
            *(uint4*)&Bs[nb2][br][(bc + 192) ^ bsw] = u;
        }
        __syncthreads();
        buf ^= 1;
    }

    #pragma unroll
    for (int mt = 0; mt < 4; mt++) {
        const int row = bm + wm + mt * 16 + gid;
        #pragma unroll
        for (int nt = 0; nt < 8; nt++) {
            const int col = bn + wn + nt * 8 + 2 * tig;
            *(float2*)&Cm[(size_t)row * N + col]       = make_float2(acc[mt][nt][0], acc[mt][nt][1]);
            *(float2*)&Cm[(size_t)(row + 8) * N + col] = make_float2(acc[mt][nt][2], acc[mt][nt][3]);
        }
    }
}

// ---------------- beta/alpha: sigmoid(x @ W_b), sigmoid(x @ W_a) -------------
__global__ void __launch_bounds__(128)
ba_kernel(const float* __restrict__ x, const float* __restrict__ Wb,
          const float* __restrict__ Wa, float* __restrict__ beta,
          float* __restrict__ alpha)
{
    __shared__ float xs[CC];
    const int row = blockIdx.x;
    const float* xr = x + (size_t)row * CC;
    for (int i = threadIdx.x; i < CC; i += 128) xs[i] = xr[i];
    __syncthreads();

    const int g = threadIdx.x >> 2;
    const int l = threadIdx.x & 3;
    const float* W = (g < 16) ? Wb : Wa;
    const int h = g & 15;
    float s = 0.f;
    for (int cidx = l; cidx < CC; cidx += 4)
        s = fmaf(xs[cidx], W[cidx * HH + h], s);
    s += __shfl_down_sync(0xffffffffu, s, 2);
    s += __shfl_down_sync(0xffffffffu, s, 1);
    if (l == 0) {
        float v = 1.f / (1.f + expf(-s));
        if (g < 16) beta[(size_t)row * HH + h] = v;
        else        alpha[(size_t)row * HH + h] = v;
    }
}

// ---------------- causal depthwise conv(K=4) + silu + l2norm of q,k ----------
__global__ void __launch_bounds__(256)
conv_kernel(const float* __restrict__ qkvz, const float* __restrict__ conv_w,
            const float* __restrict__ conv_state, const int* __restrict__ input_pos,
            float* __restrict__ y_out)
{
    __shared__ float ybuf[CONV_DIM];
    __shared__ float norms[32];

    const int bt = blockIdx.x;
    const int b = bt >> 11;
    const int t = bt & 2047;
    const float keep = (input_pos[0] == 0) ? 0.f : 1.f;

    for (int c = threadIdx.x; c < CONV_DIM; c += 256) {
        float4 w = *(const float4*)&conv_w[c * 4];
        float in[4];
        #pragma unroll
        for (int j = 0; j < 4; j++) {
            int tau = t + j - 3;
            float v;
            if (tau >= 0) v = qkvz[((size_t)(b * TT + tau)) * QKVZ_N + c];
            else          v = keep * conv_state[((size_t)b * CONV_DIM + c) * 4 + (t + 1 + j)];
            in[j] = v;
        }
        float acc = in[0] * w.x + in[1] * w.y + in[2] * w.z + in[3] * w.w;
        float sig = 1.f / (1.f + expf(-acc));
        ybuf[c] = acc * sig;
    }
    __syncthreads();

    const int wid = threadIdx.x >> 5;
    const int lane = threadIdx.x & 31;
    for (int hh = wid; hh < 32; hh += 8) {
        int base = (hh < 16) ? hh * 128 : KEY_DIM + (hh - 16) * 128;
        float ss = 0.f;
        #pragma unroll
        for (int i = 0; i < 4; i++) {
            float v = ybuf[base + lane + i * 32];
            ss = fmaf(v, v, ss);
        }
        #pragma unroll
        for (int off = 16; off > 0; off >>= 1)
            ss += __shfl_xor_sync(0xffffffffu, ss, off);
        if (lane == 0) norms[hh] = fmaxf(sqrtf(ss), 1e-12f);
    }
    __syncthreads();

    float* yr = y_out + (size_t)bt * CONV_DIM;
    for (int c = threadIdx.x; c < CONV_DIM; c += 256) {
        float v = ybuf[c];
        if (c < 2 * KEY_DIM) v /= norms[c >> 7];
        yr[c] = v;
    }
}

// ---------------- gated linear-attention recurrence --------------------------
__global__ void __launch_bounds__(256)
recur_kernel(const float* __restrict__ y, const float* __restrict__ beta,
             const float* __restrict__ alpha, const float* __restrict__ rstate,
             const int* __restrict__ input_pos, float* __restrict__ att)
{
    __shared__ float qs[128], ks[128], vs[32];
    __shared__ float red[8][33];

    const int bh = blockIdx.y;
    const int b = bh >> 4, h = bh & 15;
    const int dvb = blockIdx.x * 32;
    const int tid = threadIdx.x;
    const int dvl = tid & 31;
    const int dkg = tid >> 5;
    const int dv = dvb + dvl;
    const float keep = (input_pos[0] == 0) ? 0.f : 1.f;

    float s[16];
    #pragma unroll
    for (int i = 0; i < 16; i++)
        s[i] = keep * rstate[((size_t)bh * 128 + (dkg * 16 + i)) * 128 + dv];

    const float* ybase = y + (size_t)b * TT * CONV_DIM + h * 128;
    const float* arow = alpha + (size_t)b * TT * HH + h;
    const float* brow = beta  + (size_t)b * TT * HH + h;

    for (int t = 0; t < TT; t++) {
        const float* yr = ybase + (size_t)t * CONV_DIM;
        if (tid < 128) qs[tid] = yr[tid];
        else           ks[tid - 128] = yr[KEY_DIM + (tid - 128)];
        if (tid < 32)  vs[tid] = yr[2 * KEY_DIM + dvb + tid];
        __syncthreads();

        float a = arow[(size_t)t * HH];
        float bta = brow[(size_t)t * HH];
        float bv = bta * vs[dvl];
        float po = 0.f;
        #pragma unroll
        for (int i = 0; i < 16; i++) {
            int dk = dkg * 16 + i;
            s[i] = fmaf(a, s[i], bv * ks[dk]);
            po = fmaf(qs[dk], s[i], po);
        }
        red[dkg][dvl] = po;
        __syncthreads();
        if (dkg == 0) {
            float o = 0.f;
            #pragma unroll
            for (int g = 0; g < 8; g++) o += red[g][dvl];
            att[((size_t)(b * TT + t)) * VALUE_DIM + h * 128 + dv] = o;
        }
    }
}

// ---------------- rmsnorm * norm_w * sigmoid(z) ------------------------------
__global__ void __launch_bounds__(256)
gate_kernel(const float* __restrict__ att, const float* __restrict__ qkvz,
            const float* __restrict__ norm_w, float* __restrict__ go)
{
    const int bt = blockIdx.x;
    const int wid = threadIdx.x >> 5;
    const int lane = threadIdx.x & 31;

    #pragma unroll
    for (int k = 0; k < 2; k++) {
        const int hh = wid * 2 + k;
        const float* ar = att + (size_t)bt * VALUE_DIM + hh * 128;
        float v[4];
        float ss = 0.f;
        #pragma unroll
        for (int i = 0; i < 4; i++) {
            v[i] = ar[lane + i * 32];
            ss = fmaf(v[i], v[i], ss);
        }
        #pragma unroll
        for (int off = 16; off > 0; off >>= 1)
            ss += __shfl_xor_sync(0xffffffffu, ss, off);
        float scale = rsqrtf(ss * (1.f / 128.f) + 1e-6f);
        const float* zr = qkvz + (size_t)bt * QKVZ_N + CONV_DIM + hh * 128;
        float* gr = go + (size_t)bt * VALUE_DIM + hh * 128;
        #pragma unroll
        for (int i = 0; i < 4; i++) {
            int dvi = lane + i * 32;
            float z = zr[dvi];
            float sig = 1.f / (1.f + expf(-z));
            gr[dvi] = v[i] * scale * norm_w[dvi] * sig;
        }
    }
}

// ---------------- launch -----------------------------------------------------
extern "C" void kernel_launch(void* const* d_in, const int* in_sizes, int n_in,
                              void* d_out, int out_size)
{
    const float* x          = (const float*)d_in[0];
    const int*   input_pos  = (const int*)  d_in[1];
    const float* W_qkvz     = (const float*)d_in[2];
    const float* W_b        = (const float*)d_in[3];
    const float* W_a        = (const float*)d_in[4];
    const float* conv_w     = (const float*)d_in[5];
    const float* norm_w     = (const float*)d_in[6];
    const float* W_out      = (const float*)d_in[7];
    const float* conv_state = (const float*)d_in[8];
    const float* rec_state  = (const float*)d_in[9];
    float* out = (float*)d_out;

    float *qkvz, *y, *beta, *alpha, *attb, *gob;
    cudaGetSymbolAddress((void**)&qkvz, g_qkvz);
    cudaGetSymbolAddress((void**)&y,    g_y);
    cudaGetSymbolAddress((void**)&beta, g_beta);
    cudaGetSymbolAddress((void**)&alpha,g_alpha);
    cudaGetSymbolAddress((void**)&attb, g_att);
    cudaGetSymbolAddress((void**)&gob,  g_go);

    // 1) qkvz = x @ W_qkvz      (4096 x 8192 x 2048), tf32 tensor cores
    tf32gemm<<<dim3(QKVZ_N / 256, BT / 128), 256>>>(x, W_qkvz, qkvz, BT, QKVZ_N, CC);
    // 2) beta/alpha
    ba_kernel<<<BT, 128>>>(x, W_b, W_a, beta, alpha);
    // 3) conv + silu + l2norm
    conv_kernel<<<BT, 256>>>(qkvz, conv_w, conv_state, input_pos, y);
    // 4) recurrence
    recur_kernel<<<dim3(4, 32), 256>>>(y, beta, alpha, rec_state, input_pos, attb);
    // 5) rmsnorm + gate
    gate_kernel<<<BT, 256>>>(attb, qkvz, norm_w, gob);
    // 6) out = gated @ W_out    (4096 x 2048 x 2048), tf32 tensor cores
    tf32gemm<<<dim3(CC / 256, BT / 128), 256>>>(gob, W_out, out, BT, CC, CC);
}